// round 6
// baseline (speedup 1.0000x reference)
#include <cuda_runtime.h>
#include <cuda_bf16.h>
#include <cstdint>

// ---------------------------------------------------------------------------
// GCN 2-layer + FC, aggregation-first + CSR-gather form.
//   CSR by destination (deg -> scan -> fill), rebuilt each call (no caching).
//   layer1: agg1[i] = xs[i] + sum_{r in nbr(i)} xs[r],  xs = x*dinv   (16-wide)
//           x2 = relu((dinv*agg1) @ W1 + b1); hs2 = (x2 @ W2)*dinv
//   layer2: agg2[i] = hs2[i] + sum hs2[r]
//           out = relu(dinv*agg2 + b2) @ fcW + fcb
// Gather mapping: 8 threads/node (4 chunks x 2 edge parities), unroll x2
// => 4 feature loads in flight per chunk (latency hiding), shfl pair-reduce.
// edge_index is int32.
// ---------------------------------------------------------------------------

#define NMAX 131072
#define EMAX 2097152

__device__ int   g_deg [NMAX];
__device__ int   g_off [NMAX];
__device__ int   g_cur [NMAX];
__device__ int   g_bsum[512];
__device__ int   g_esrc[EMAX];
__device__ float g_dinv[NMAX];
__device__ float g_xs  [NMAX * 16];
__device__ float g_agg1[NMAX * 16];
__device__ float g_hs2 [NMAX * 16];
__device__ float g_agg2[NMAX * 16];

__global__ void k_zero(int n) {
    int i = blockIdx.x * blockDim.x + threadIdx.x;
    if (i < n) g_deg[i] = 0;
}

__global__ void k_deg(const int* __restrict__ dst, int E) {
    int e = blockIdx.x * blockDim.x + threadIdx.x;
    if (e < E) atomicAdd(&g_deg[dst[e]], 1);      // no return -> RED
}

// block exclusive scan of deg via warp shuffles; block totals -> g_bsum
__global__ void k_scan1(int n) {
    __shared__ int wsum[8];
    int t = threadIdx.x, i = blockIdx.x * 256 + t;
    int lane = t & 31, w = t >> 5;
    int v = (i < n) ? g_deg[i] : 0;
    int s = v;
#pragma unroll
    for (int o = 1; o < 32; o <<= 1) {
        int x = __shfl_up_sync(0xffffffffu, s, o);
        if (lane >= o) s += x;
    }
    if (lane == 31) wsum[w] = s;
    __syncthreads();
    if (w == 0) {
        int ws = (lane < 8) ? wsum[lane] : 0;
#pragma unroll
        for (int o = 1; o < 8; o <<= 1) {
            int x = __shfl_up_sync(0xffffffffu, ws, o);
            if (lane >= o) ws += x;
        }
        if (lane < 8) wsum[lane] = ws;
    }
    __syncthreads();
    int base = (w > 0) ? wsum[w - 1] : 0;
    int incl = s + base;
    if (i < n) g_off[i] = incl - v;               // block-local exclusive
    if (t == 255) g_bsum[blockIdx.x] = incl;      // block total
}

// finalize offsets (redundant per-block prefix over bsum) + cursors + pre (dinv, xs)
__global__ void k_finalize(const float* __restrict__ x, int n, int nb) {
    __shared__ int sprefix;
    int t = threadIdx.x, b = blockIdx.x;
    if (t < 32) {
        int p = 0;
        for (int k = t; k < b && k < nb; k += 32) p += g_bsum[k];
#pragma unroll
        for (int o = 16; o; o >>= 1) p += __shfl_xor_sync(0xffffffffu, p, o);
        if (t == 0) sprefix = p;
    }
    __syncthreads();
    int i = b * 256 + t;
    if (i >= n) return;
    int o = g_off[i] + sprefix;
    g_off[i] = o;
    g_cur[i] = o;
    float dinv = rsqrtf((float)(g_deg[i] + 1));
    g_dinv[i] = dinv;
    const float4* xp = reinterpret_cast<const float4*>(x + (size_t)i * 16);
    float4* xsp = reinterpret_cast<float4*>(g_xs + (size_t)i * 16);
#pragma unroll
    for (int q = 0; q < 4; q++) {
        float4 tv = xp[q];
        tv.x *= dinv; tv.y *= dinv; tv.z *= dinv; tv.w *= dinv;
        xsp[q] = tv;
    }
}

// fill CSR adjacency: for each edge, append src to dst's list
__global__ void k_fill(const int* __restrict__ src, const int* __restrict__ dst, int E) {
    int e = blockIdx.x * blockDim.x + threadIdx.x;
    if (e >= E) return;
    int t = dst[e];
    int p = atomicAdd(&g_cur[t], 1);
    g_esrc[p] = src[e];
}

// gather: 8 threads per node: chunk c = sub>>1, parity p = sub&1.
// Each thread walks every other neighbor, unrolled x2 (4 loads in flight/chunk).
__device__ __forceinline__ void gather_body(const float* __restrict__ msg,
                                            float* __restrict__ agg, int n) {
    int idx = blockIdx.x * blockDim.x + threadIdx.x;
    int i = idx >> 3, sub = idx & 7;
    int c = sub >> 1, p = sub & 1;
    bool live = (i < n);
    if (!live) i = n - 1;                          // keep lanes in shfl
    const float4* m4 = reinterpret_cast<const float4*>(msg);
    float4 s = make_float4(0.f, 0.f, 0.f, 0.f);
    if (p == 0) s = __ldg(m4 + (size_t)i * 4 + c); // self loop
    int off = g_off[i];
    int end = off + g_deg[i];
    int j = off + p;
    for (; j + 2 < end; j += 4) {
        int r0 = g_esrc[j], r1 = g_esrc[j + 2];
        float4 a = __ldg(m4 + (size_t)r0 * 4 + c);
        float4 b = __ldg(m4 + (size_t)r1 * 4 + c);
        s.x += a.x + b.x; s.y += a.y + b.y; s.z += a.z + b.z; s.w += a.w + b.w;
    }
    if (j < end) {
        int r = g_esrc[j];
        float4 a = __ldg(m4 + (size_t)r * 4 + c);
        s.x += a.x; s.y += a.y; s.z += a.z; s.w += a.w;
    }
    s.x += __shfl_xor_sync(0xffffffffu, s.x, 1);
    s.y += __shfl_xor_sync(0xffffffffu, s.y, 1);
    s.z += __shfl_xor_sync(0xffffffffu, s.z, 1);
    s.w += __shfl_xor_sync(0xffffffffu, s.w, 1);
    if (live && p == 0)
        reinterpret_cast<float4*>(agg)[(size_t)i * 4 + c] = s;
}

__global__ void k_gather1(int n) { gather_body(g_xs,  g_agg1, n); }
__global__ void k_gather2(int n) { gather_body(g_hs2, g_agg2, n); }

// combine layer 1 + both GEMMs + relu: x2 = relu((dinv*agg1)@W1+b1); hs2 = (x2@W2)*dinv
__global__ void k_l1(const float* __restrict__ W1, const float* __restrict__ b1,
                     const float* __restrict__ W2, int n) {
    __shared__ float sW1[512];   // [16][32]
    __shared__ float sW2[512];   // [32][16]
    __shared__ float sb1[32];
    for (int i = threadIdx.x; i < 512; i += blockDim.x) { sW1[i] = W1[i]; sW2[i] = W2[i]; }
    if (threadIdx.x < 32) sb1[threadIdx.x] = b1[threadIdx.x];
    __syncthreads();
    int i = blockIdx.x * blockDim.x + threadIdx.x;
    if (i >= n) return;

    float dinv = g_dinv[i];
    float t[16];
    const float4* ap = reinterpret_cast<const float4*>(g_agg1 + (size_t)i * 16);
#pragma unroll
    for (int q = 0; q < 4; q++) {
        float4 a = ap[q];
        t[4*q  ] = a.x * dinv;
        t[4*q+1] = a.y * dinv;
        t[4*q+2] = a.z * dinv;
        t[4*q+3] = a.w * dinv;
    }

    float x2[32];
#pragma unroll
    for (int j = 0; j < 32; j++) {
        float s = sb1[j];
#pragma unroll
        for (int k = 0; k < 16; k++) s = fmaf(t[k], sW1[k*32 + j], s);
        x2[j] = fmaxf(s, 0.f);
    }

    float4* hp = reinterpret_cast<float4*>(g_hs2 + (size_t)i * 16);
#pragma unroll
    for (int q = 0; q < 4; q++) {
        float h[4];
#pragma unroll
        for (int jj = 0; jj < 4; jj++) {
            int j = 4*q + jj;
            float s = 0.f;
#pragma unroll
            for (int k = 0; k < 32; k++) s = fmaf(x2[k], sW2[k*16 + j], s);
            h[jj] = s * dinv;
        }
        hp[q] = make_float4(h[0], h[1], h[2], h[3]);
    }
}

// combine layer 2 + relu + FC head
__global__ void k_final(const float* __restrict__ b2, const float* __restrict__ fcW,
                        const float* __restrict__ fcb, float* __restrict__ out, int n) {
    __shared__ float sb[16];
    __shared__ float sw[16];
    if (threadIdx.x < 16) { sb[threadIdx.x] = b2[threadIdx.x]; sw[threadIdx.x] = fcW[threadIdx.x]; }
    __syncthreads();
    int i = blockIdx.x * blockDim.x + threadIdx.x;
    if (i >= n) return;

    float dinv = g_dinv[i];
    float s = fcb[0];
    const float4* ap = reinterpret_cast<const float4*>(g_agg2 + (size_t)i * 16);
#pragma unroll
    for (int q = 0; q < 4; q++) {
        float4 a = ap[q];
        float v0 = fmaxf(fmaf(dinv, a.x, sb[4*q  ]), 0.f);
        float v1 = fmaxf(fmaf(dinv, a.y, sb[4*q+1]), 0.f);
        float v2 = fmaxf(fmaf(dinv, a.z, sb[4*q+2]), 0.f);
        float v3 = fmaxf(fmaf(dinv, a.w, sb[4*q+3]), 0.f);
        s = fmaf(v0, sw[4*q], fmaf(v1, sw[4*q+1], fmaf(v2, sw[4*q+2], fmaf(v3, sw[4*q+3], s))));
    }
    out[i] = s;
}

extern "C" void kernel_launch(void* const* d_in, const int* in_sizes, int n_in,
                              void* d_out, int out_size) {
    const int*   ei  = (const int*)d_in[0];     // [2, E] int32
    const float* x   = (const float*)d_in[1];   // [N, 16]
    const float* W1  = (const float*)d_in[2];   // [16, 32]
    const float* b1  = (const float*)d_in[3];   // [32]
    const float* W2  = (const float*)d_in[4];   // [32, 16]
    const float* b2  = (const float*)d_in[5];   // [16]
    const float* fcW = (const float*)d_in[6];   // [16, 1]
    const float* fcb = (const float*)d_in[7];   // [1]
    float*       out = (float*)d_out;           // [N, 1]

    const int E = in_sizes[0] / 2;
    const int n = in_sizes[1] / 16;
    const int* src = ei;
    const int* dst = ei + E;

    const int T  = 256;
    const int nb = (n + 255) / 256;             // <= 512

    k_zero    <<<(n + T - 1) / T, T>>>(n);
    k_deg     <<<(E + T - 1) / T, T>>>(dst, E);
    k_scan1   <<<nb, 256>>>(n);
    k_finalize<<<nb, 256>>>(x, n, nb);
    k_fill    <<<(E + T - 1) / T, T>>>(src, dst, E);
    k_gather1 <<<((long long)n * 8 + T - 1) / T, T>>>(n);
    k_l1      <<<(n + T - 1) / T, T>>>(W1, b1, W2, n);
    k_gather2 <<<((long long)n * 8 + T - 1) / T, T>>>(n);
    k_final   <<<(n + T - 1) / T, T>>>(b2, fcW, fcb, out, n);
}